// round 5
// baseline (speedup 1.0000x reference)
#include <cuda_runtime.h>
#include <cuda_bf16.h>
#include <math.h>

// Problem constants
#define PB  2
#define PS  2048
#define PD  4096
#define PH  32
#define PKVH 8
#define PHD 128
#define ROWS (PB*PS)            // 4096 tokens
#define QCOLS (PH*PHD)          // 4096
#define KVCOLS (PKVH*PHD)       // 1024

// ---------------------------------------------------------------------------
// Scratch (static device allocations — allowed; cudaMalloc is not)
// ---------------------------------------------------------------------------
__device__ float g_Q[(size_t)ROWS * QCOLS];   // 64 MB
__device__ float g_K[(size_t)ROWS * KVCOLS];  // 16 MB
__device__ float g_V[(size_t)ROWS * KVCOLS];  // 16 MB
__device__ float g_O[(size_t)ROWS * QCOLS];   // 64 MB

// ---------------------------------------------------------------------------
// SGEMM: C[M,N] = A[M,K] @ B[K,N], all row-major, fp32.
// BM=BN=128, BK=16, 256 threads, 8x8 per-thread tile.
// M,N multiples of 128; K multiple of 16 (true for all calls here).
// ---------------------------------------------------------------------------
#define GBM 128
#define GBN 128
#define GBK 16
#define APAD 132   // 128+4 to de-conflict transposed A stores

__global__ __launch_bounds__(256, 2)
void sgemm128(const float* __restrict__ A, const float* __restrict__ B,
              float* __restrict__ C, int M, int N, int K) {
    __shared__ float As[GBK][APAD];   // A transposed: As[kk][m]
    __shared__ float Bs[GBK][GBN];

    const int tid = threadIdx.x;
    const int tx  = tid & 15;         // column group
    const int ty  = tid >> 4;         // row group
    const int cBase = blockIdx.x * GBN;
    const int rBase = blockIdx.y * GBM;

    const float* Aptr = A + (size_t)rBase * K;
    const float* Bptr = B + cBase;

    float acc[8][8];
#pragma unroll
    for (int m = 0; m < 8; m++)
#pragma unroll
        for (int n = 0; n < 8; n++) acc[m][n] = 0.f;

    for (int k0 = 0; k0 < K; k0 += GBK) {
        // Load A tile (128x16) -> transposed smem. 512 float4, 2/thread.
#pragma unroll
        for (int r = 0; r < 2; r++) {
            int t = tid + r * 256;
            int arow = t >> 2;
            int ac4  = t & 3;
            float4 v = *(const float4*)(Aptr + (size_t)arow * K + k0 + ac4 * 4);
            As[ac4*4+0][arow] = v.x;
            As[ac4*4+1][arow] = v.y;
            As[ac4*4+2][arow] = v.z;
            As[ac4*4+3][arow] = v.w;
        }
        // Load B tile (16x128) direct. 512 float4, 2/thread.
#pragma unroll
        for (int r = 0; r < 2; r++) {
            int t = tid + r * 256;
            int brow = t >> 5;
            int bc4  = t & 31;
            *(float4*)(&Bs[brow][bc4*4]) =
                *(const float4*)(Bptr + (size_t)(k0 + brow) * N + bc4 * 4);
        }
        __syncthreads();

#pragma unroll
        for (int kk = 0; kk < GBK; kk++) {
            float a[8], bb[8];
            float4 a0 = *(const float4*)(&As[kk][ty*8]);
            float4 a1 = *(const float4*)(&As[kk][ty*8+4]);
            float4 b0 = *(const float4*)(&Bs[kk][tx*8]);
            float4 b1 = *(const float4*)(&Bs[kk][tx*8+4]);
            a[0]=a0.x; a[1]=a0.y; a[2]=a0.z; a[3]=a0.w;
            a[4]=a1.x; a[5]=a1.y; a[6]=a1.z; a[7]=a1.w;
            bb[0]=b0.x; bb[1]=b0.y; bb[2]=b0.z; bb[3]=b0.w;
            bb[4]=b1.x; bb[5]=b1.y; bb[6]=b1.z; bb[7]=b1.w;
#pragma unroll
            for (int m = 0; m < 8; m++)
#pragma unroll
                for (int n = 0; n < 8; n++)
                    acc[m][n] += a[m] * bb[n];
        }
        __syncthreads();
    }

#pragma unroll
    for (int m = 0; m < 8; m++) {
        float* crow = C + (size_t)(rBase + ty*8 + m) * N + cBase + tx*8;
        *(float4*)(crow)     = make_float4(acc[m][0], acc[m][1], acc[m][2], acc[m][3]);
        *(float4*)(crow + 4) = make_float4(acc[m][4], acc[m][5], acc[m][6], acc[m][7]);
    }
}

// ---------------------------------------------------------------------------
// RoPE (interleaved even/odd pairs), optional uniform scale (folds 1/sqrt(HD)
// into Q). t: [rows, nHeads*128] row-major; rows = B*S; seq index = row % S.
// ---------------------------------------------------------------------------
__global__ void rope_kernel(float* __restrict__ t,
                            const float* __restrict__ cos_t,
                            const float* __restrict__ sin_t,
                            int nHeads, int total, float scale) {
    int idx = blockIdx.x * blockDim.x + threadIdx.x;
    if (idx >= total) return;
    int pair = idx & 63;                 // HD/2 = 64
    int head = (idx >> 6) % nHeads;
    int row  = idx / (64 * nHeads);
    int s    = row & (PS - 1);
    float c  = cos_t[s * 64 + pair];
    float sn = sin_t[s * 64 + pair];
    float2* p = (float2*)(t + (size_t)row * (nHeads * 128) + head * 128 + pair * 2);
    float2 v = *p;
    float vr = (v.x * c - v.y * sn) * scale;
    float vi = (v.x * sn + v.y * c) * scale;
    *p = make_float2(vr, vi);
}

// ---------------------------------------------------------------------------
// Fused causal flash attention, fp32. GQA REP=4.
// grid = (S/64, H, B); 256 threads = 16x16; each thread: 4 q-rows x (4 score
// cols | 8 out cols). Q pre-scaled by 1/sqrt(HD).
// ---------------------------------------------------------------------------
#define FQ 64
#define FK 64
#define FPAD 132   // row stride for 128-wide tiles
#define PPAD 65    // row stride for P tile

__global__ __launch_bounds__(256, 1)
void flash_attn(const float* __restrict__ Q, const float* __restrict__ K,
                const float* __restrict__ V, float* __restrict__ O) {
    extern __shared__ float sm[];
    float* Qs = sm;                    // [64][132]
    float* Ks = Qs + FQ * FPAD;        // [64][132]
    float* Vs = Ks + FK * FPAD;        // [64][132]
    float* Ps = Vs + FK * FPAD;        // [64][65]

    const int tid = threadIdx.x;
    const int tx  = tid & 15;
    const int ty  = tid >> 4;
    const int qb  = blockIdx.x;
    const int h   = blockIdx.y;
    const int b   = blockIdx.z;
    const int kvh = h >> 2;            // REP = 4

    const int qRow0 = b * PS + qb * FQ;
    const float* Qg = Q + (size_t)qRow0 * QCOLS + h * PHD;

    // Load Q tile (64x128): 2048 float4, 8 per thread, coalesced.
#pragma unroll
    for (int r = 0; r < 8; r++) {
        int t  = tid + r * 256;
        int i  = t >> 5;
        int d4 = t & 31;
        *(float4*)(&Qs[i * FPAD + d4 * 4]) =
            *(const float4*)(Qg + (size_t)i * QCOLS + d4 * 4);
    }

    float out[4][8];
    float m_i[4], l_i[4];
#pragma unroll
    for (int ii = 0; ii < 4; ii++) {
        m_i[ii] = -1e30f; l_i[ii] = 0.f;
#pragma unroll
        for (int c = 0; c < 8; c++) out[ii][c] = 0.f;
    }
    __syncthreads();

    const int nkt = qb + 1;   // causal: only k-tiles up to the diagonal
    for (int kt = 0; kt < nkt; kt++) {
        const int kRow0 = b * PS + kt * FK;
        const float* Kg = K + (size_t)kRow0 * KVCOLS + kvh * PHD;
        const float* Vg = V + (size_t)kRow0 * KVCOLS + kvh * PHD;
#pragma unroll
        for (int r = 0; r < 8; r++) {
            int t  = tid + r * 256;
            int j  = t >> 5;
            int d4 = t & 31;
            *(float4*)(&Ks[j * FPAD + d4 * 4]) =
                *(const float4*)(Kg + (size_t)j * KVCOLS + d4 * 4);
            *(float4*)(&Vs[j * FPAD + d4 * 4]) =
                *(const float4*)(Vg + (size_t)j * KVCOLS + d4 * 4);
        }
        __syncthreads();

        // Scores: s[ii][jj] = Qs[4ty+ii,:] . Ks[4tx+jj,:]
        float s[4][4];
#pragma unroll
        for (int ii = 0; ii < 4; ii++)
#pragma unroll
            for (int jj = 0; jj < 4; jj++) s[ii][jj] = 0.f;

#pragma unroll 8
        for (int d4 = 0; d4 < 32; d4++) {
            float4 qv[4], kv[4];
#pragma unroll
            for (int ii = 0; ii < 4; ii++)
                qv[ii] = *(const float4*)(&Qs[(4*ty+ii) * FPAD + d4 * 4]);
#pragma unroll
            for (int jj = 0; jj < 4; jj++)
                kv[jj] = *(const float4*)(&Ks[(4*tx+jj) * FPAD + d4 * 4]);
#pragma unroll
            for (int ii = 0; ii < 4; ii++)
#pragma unroll
                for (int jj = 0; jj < 4; jj++)
                    s[ii][jj] += qv[ii].x * kv[jj].x + qv[ii].y * kv[jj].y
                               + qv[ii].z * kv[jj].z + qv[ii].w * kv[jj].w;
        }

        // Causal mask (only the diagonal tile has masked entries)
        if (kt == qb) {
#pragma unroll
            for (int ii = 0; ii < 4; ii++)
#pragma unroll
                for (int jj = 0; jj < 4; jj++)
                    if (4*tx + jj > 4*ty + ii) s[ii][jj] = -1e30f;
        }

        // Online softmax. Rows are owned by 16 consecutive lanes (same ty),
        // which sit inside one 16-lane shuffle group.
        float alpha[4];
#pragma unroll
        for (int ii = 0; ii < 4; ii++) {
            float mx = fmaxf(fmaxf(s[ii][0], s[ii][1]), fmaxf(s[ii][2], s[ii][3]));
#pragma unroll
            for (int off = 1; off < 16; off <<= 1)
                mx = fmaxf(mx, __shfl_xor_sync(0xffffffffu, mx, off));
            float mnew = fmaxf(m_i[ii], mx);
            alpha[ii] = __expf(m_i[ii] - mnew);
            float rs = 0.f;
#pragma unroll
            for (int jj = 0; jj < 4; jj++) {
                float p = __expf(s[ii][jj] - mnew);
                s[ii][jj] = p;
                rs += p;
            }
#pragma unroll
            for (int off = 1; off < 16; off <<= 1)
                rs += __shfl_xor_sync(0xffffffffu, rs, off);
            l_i[ii] = l_i[ii] * alpha[ii] + rs;
            m_i[ii] = mnew;
        }

        // Stage P through smem for the PV GEMM.
#pragma unroll
        for (int ii = 0; ii < 4; ii++)
#pragma unroll
            for (int jj = 0; jj < 4; jj++)
                Ps[(4*ty+ii) * PPAD + 4*tx + jj] = s[ii][jj];
        __syncthreads();

        // Rescale accumulators, then out += P @ V.
#pragma unroll
        for (int ii = 0; ii < 4; ii++)
#pragma unroll
            for (int c = 0; c < 8; c++) out[ii][c] *= alpha[ii];

#pragma unroll 4
        for (int j = 0; j < FK; j++) {
            float4 v0 = *(const float4*)(&Vs[j * FPAD + tx * 8]);
            float4 v1 = *(const float4*)(&Vs[j * FPAD + tx * 8 + 4]);
#pragma unroll
            for (int ii = 0; ii < 4; ii++) {
                float p = Ps[(4*ty+ii) * PPAD + j];
                out[ii][0] += p * v0.x; out[ii][1] += p * v0.y;
                out[ii][2] += p * v0.z; out[ii][3] += p * v0.w;
                out[ii][4] += p * v1.x; out[ii][5] += p * v1.y;
                out[ii][6] += p * v1.z; out[ii][7] += p * v1.w;
            }
        }
        __syncthreads();   // before next tile overwrites Ks/Vs/Ps
    }

    // Normalize and write O in [B*S, H*HD] layout.
#pragma unroll
    for (int ii = 0; ii < 4; ii++) {
        float il = 1.f / l_i[ii];
        float* orow = O + (size_t)(qRow0 + 4*ty + ii) * QCOLS + h * PHD + tx * 8;
        *(float4*)(orow)     = make_float4(out[ii][0]*il, out[ii][1]*il,
                                           out[ii][2]*il, out[ii][3]*il);
        *(float4*)(orow + 4) = make_float4(out[ii][4]*il, out[ii][5]*il,
                                           out[ii][6]*il, out[ii][7]*il);
    }
}

// ---------------------------------------------------------------------------
// Launch
// ---------------------------------------------------------------------------
extern "C" void kernel_launch(void* const* d_in, const int* in_sizes, int n_in,
                              void* d_out, int out_size) {
    (void)in_sizes; (void)n_in; (void)out_size;

    const float* x  = (const float*)d_in[0];   // [B,S,D]
    const float* fc = (const float*)d_in[1];   // [S, HD/2]
    const float* fs = (const float*)d_in[2];   // [S, HD/2]
    const float* Wq = (const float*)d_in[3];   // [D, H*HD]
    const float* Wk = (const float*)d_in[4];   // [D, KVH*HD]
    const float* Wv = (const float*)d_in[5];   // [D, KVH*HD]
    const float* Wo = (const float*)d_in[6];   // [H*HD, D]
    float* out = (float*)d_out;                // [B,S,D]

    float *Qb, *Kb, *Vb, *Ob;
    cudaGetSymbolAddress((void**)&Qb, g_Q);
    cudaGetSymbolAddress((void**)&Kb, g_K);
    cudaGetSymbolAddress((void**)&Vb, g_V);
    cudaGetSymbolAddress((void**)&Ob, g_O);

    // 1) QKV projections
    sgemm128<<<dim3(QCOLS/GBN,  ROWS/GBM), 256>>>(x, Wq, Qb, ROWS, QCOLS,  PD);
    sgemm128<<<dim3(KVCOLS/GBN, ROWS/GBM), 256>>>(x, Wk, Kb, ROWS, KVCOLS, PD);
    sgemm128<<<dim3(KVCOLS/GBN, ROWS/GBM), 256>>>(x, Wv, Vb, ROWS, KVCOLS, PD);

    // 2) RoPE (fold 1/sqrt(HD) into Q)
    const float qscale = 0.08838834764831845f;   // 1/sqrt(128)
    {
        int totalQ = ROWS * PH * 64;
        rope_kernel<<<(totalQ + 255) / 256, 256>>>(Qb, fc, fs, PH, totalQ, qscale);
        int totalK = ROWS * PKVH * 64;
        rope_kernel<<<(totalK + 255) / 256, 256>>>(Kb, fc, fs, PKVH, totalK, 1.0f);
    }

    // 3) Fused causal flash attention
    {
        size_t smem = (size_t)(3 * FQ * FPAD + FQ * PPAD) * sizeof(float); // ~115 KB
        cudaFuncSetAttribute(flash_attn,
                             cudaFuncAttributeMaxDynamicSharedMemorySize, (int)smem);
        flash_attn<<<dim3(PS/FQ, PH, PB), 256, smem>>>(Qb, Kb, Vb, Ob);
    }

    // 4) Output projection -> d_out
    sgemm128<<<dim3(PD/GBN, ROWS/GBM), 256>>>(Ob, Wo, out, ROWS, PD, QCOLS);
}

// round 6
// speedup vs baseline: 1.0007x; 1.0007x over previous
#include <cuda_runtime.h>
#include <cuda_bf16.h>
#include <math.h>

// Problem constants
#define PB  2
#define PS  2048
#define PD  4096
#define PH  32
#define PKVH 8
#define PHD 128
#define ROWS (PB*PS)            // 4096 tokens
#define QCOLS (PH*PHD)          // 4096
#define KVCOLS (PKVH*PHD)       // 1024

// ---------------------------------------------------------------------------
// Scratch (static device allocations — allowed; cudaMalloc is not)
// ---------------------------------------------------------------------------
__device__ float g_Q[(size_t)ROWS * QCOLS];   // 64 MB
__device__ float g_K[(size_t)ROWS * KVCOLS];  // 16 MB
__device__ float g_V[(size_t)ROWS * KVCOLS];  // 16 MB
__device__ float g_O[(size_t)ROWS * QCOLS];   // 64 MB

// ---------------------------------------------------------------------------
// SGEMM: C[M,N] = A[M,K] @ B[K,N], all row-major, fp32.
// BM=BN=128, BK=16, 256 threads, 8x8 per-thread tile.
// M,N multiples of 128; K multiple of 16 (true for all calls here).
// ---------------------------------------------------------------------------
#define GBM 128
#define GBN 128
#define GBK 16
#define APAD 132   // 128+4 to de-conflict transposed A stores

__global__ __launch_bounds__(256, 2)
void sgemm128(const float* __restrict__ A, const float* __restrict__ B,
              float* __restrict__ C, int M, int N, int K) {
    __shared__ float As[GBK][APAD];   // A transposed: As[kk][m]
    __shared__ float Bs[GBK][GBN];

    const int tid = threadIdx.x;
    const int tx  = tid & 15;         // column group
    const int ty  = tid >> 4;         // row group
    const int cBase = blockIdx.x * GBN;
    const int rBase = blockIdx.y * GBM;

    const float* Aptr = A + (size_t)rBase * K;
    const float* Bptr = B + cBase;

    float acc[8][8];
#pragma unroll
    for (int m = 0; m < 8; m++)
#pragma unroll
        for (int n = 0; n < 8; n++) acc[m][n] = 0.f;

    for (int k0 = 0; k0 < K; k0 += GBK) {
        // Load A tile (128x16) -> transposed smem. 512 float4, 2/thread.
#pragma unroll
        for (int r = 0; r < 2; r++) {
            int t = tid + r * 256;
            int arow = t >> 2;
            int ac4  = t & 3;
            float4 v = *(const float4*)(Aptr + (size_t)arow * K + k0 + ac4 * 4);
            As[ac4*4+0][arow] = v.x;
            As[ac4*4+1][arow] = v.y;
            As[ac4*4+2][arow] = v.z;
            As[ac4*4+3][arow] = v.w;
        }
        // Load B tile (16x128) direct. 512 float4, 2/thread.
#pragma unroll
        for (int r = 0; r < 2; r++) {
            int t = tid + r * 256;
            int brow = t >> 5;
            int bc4  = t & 31;
            *(float4*)(&Bs[brow][bc4*4]) =
                *(const float4*)(Bptr + (size_t)(k0 + brow) * N + bc4 * 4);
        }
        __syncthreads();

#pragma unroll
        for (int kk = 0; kk < GBK; kk++) {
            float a[8], bb[8];
            float4 a0 = *(const float4*)(&As[kk][ty*8]);
            float4 a1 = *(const float4*)(&As[kk][ty*8+4]);
            float4 b0 = *(const float4*)(&Bs[kk][tx*8]);
            float4 b1 = *(const float4*)(&Bs[kk][tx*8+4]);
            a[0]=a0.x; a[1]=a0.y; a[2]=a0.z; a[3]=a0.w;
            a[4]=a1.x; a[5]=a1.y; a[6]=a1.z; a[7]=a1.w;
            bb[0]=b0.x; bb[1]=b0.y; bb[2]=b0.z; bb[3]=b0.w;
            bb[4]=b1.x; bb[5]=b1.y; bb[6]=b1.z; bb[7]=b1.w;
#pragma unroll
            for (int m = 0; m < 8; m++)
#pragma unroll
                for (int n = 0; n < 8; n++)
                    acc[m][n] += a[m] * bb[n];
        }
        __syncthreads();
    }

#pragma unroll
    for (int m = 0; m < 8; m++) {
        float* crow = C + (size_t)(rBase + ty*8 + m) * N + cBase + tx*8;
        *(float4*)(crow)     = make_float4(acc[m][0], acc[m][1], acc[m][2], acc[m][3]);
        *(float4*)(crow + 4) = make_float4(acc[m][4], acc[m][5], acc[m][6], acc[m][7]);
    }
}

// ---------------------------------------------------------------------------
// RoPE (interleaved even/odd pairs), optional uniform scale (folds 1/sqrt(HD)
// into Q). t: [rows, nHeads*128] row-major; rows = B*S; seq index = row % S.
// ---------------------------------------------------------------------------
__global__ void rope_kernel(float* __restrict__ t,
                            const float* __restrict__ cos_t,
                            const float* __restrict__ sin_t,
                            int nHeads, int total, float scale) {
    int idx = blockIdx.x * blockDim.x + threadIdx.x;
    if (idx >= total) return;
    int pair = idx & 63;                 // HD/2 = 64
    int head = (idx >> 6) % nHeads;
    int row  = idx / (64 * nHeads);
    int s    = row & (PS - 1);
    float c  = cos_t[s * 64 + pair];
    float sn = sin_t[s * 64 + pair];
    float2* p = (float2*)(t + (size_t)row * (nHeads * 128) + head * 128 + pair * 2);
    float2 v = *p;
    float vr = (v.x * c - v.y * sn) * scale;
    float vi = (v.x * sn + v.y * c) * scale;
    *p = make_float2(vr, vi);
}

// ---------------------------------------------------------------------------
// Fused causal flash attention, fp32. GQA REP=4.
// grid = (S/64, H, B); 256 threads = 16x16; each thread: 4 q-rows x (4 score
// cols | 8 out cols). Q pre-scaled by 1/sqrt(HD).
// ---------------------------------------------------------------------------
#define FQ 64
#define FK 64
#define FPAD 132   // row stride for 128-wide tiles
#define PPAD 65    // row stride for P tile

__global__ __launch_bounds__(256, 1)
void flash_attn(const float* __restrict__ Q, const float* __restrict__ K,
                const float* __restrict__ V, float* __restrict__ O) {
    extern __shared__ float sm[];
    float* Qs = sm;                    // [64][132]
    float* Ks = Qs + FQ * FPAD;        // [64][132]
    float* Vs = Ks + FK * FPAD;        // [64][132]
    float* Ps = Vs + FK * FPAD;        // [64][65]

    const int tid = threadIdx.x;
    const int tx  = tid & 15;
    const int ty  = tid >> 4;
    const int qb  = blockIdx.x;
    const int h   = blockIdx.y;
    const int b   = blockIdx.z;
    const int kvh = h >> 2;            // REP = 4

    const int qRow0 = b * PS + qb * FQ;
    const float* Qg = Q + (size_t)qRow0 * QCOLS + h * PHD;

    // Load Q tile (64x128): 2048 float4, 8 per thread, coalesced.
#pragma unroll
    for (int r = 0; r < 8; r++) {
        int t  = tid + r * 256;
        int i  = t >> 5;
        int d4 = t & 31;
        *(float4*)(&Qs[i * FPAD + d4 * 4]) =
            *(const float4*)(Qg + (size_t)i * QCOLS + d4 * 4);
    }

    float out[4][8];
    float m_i[4], l_i[4];
#pragma unroll
    for (int ii = 0; ii < 4; ii++) {
        m_i[ii] = -1e30f; l_i[ii] = 0.f;
#pragma unroll
        for (int c = 0; c < 8; c++) out[ii][c] = 0.f;
    }
    __syncthreads();

    const int nkt = qb + 1;   // causal: only k-tiles up to the diagonal
    for (int kt = 0; kt < nkt; kt++) {
        const int kRow0 = b * PS + kt * FK;
        const float* Kg = K + (size_t)kRow0 * KVCOLS + kvh * PHD;
        const float* Vg = V + (size_t)kRow0 * KVCOLS + kvh * PHD;
#pragma unroll
        for (int r = 0; r < 8; r++) {
            int t  = tid + r * 256;
            int j  = t >> 5;
            int d4 = t & 31;
            *(float4*)(&Ks[j * FPAD + d4 * 4]) =
                *(const float4*)(Kg + (size_t)j * KVCOLS + d4 * 4);
            *(float4*)(&Vs[j * FPAD + d4 * 4]) =
                *(const float4*)(Vg + (size_t)j * KVCOLS + d4 * 4);
        }
        __syncthreads();

        // Scores: s[ii][jj] = Qs[4ty+ii,:] . Ks[4tx+jj,:]
        float s[4][4];
#pragma unroll
        for (int ii = 0; ii < 4; ii++)
#pragma unroll
            for (int jj = 0; jj < 4; jj++) s[ii][jj] = 0.f;

#pragma unroll 8
        for (int d4 = 0; d4 < 32; d4++) {
            float4 qv[4], kv[4];
#pragma unroll
            for (int ii = 0; ii < 4; ii++)
                qv[ii] = *(const float4*)(&Qs[(4*ty+ii) * FPAD + d4 * 4]);
#pragma unroll
            for (int jj = 0; jj < 4; jj++)
                kv[jj] = *(const float4*)(&Ks[(4*tx+jj) * FPAD + d4 * 4]);
#pragma unroll
            for (int ii = 0; ii < 4; ii++)
#pragma unroll
                for (int jj = 0; jj < 4; jj++)
                    s[ii][jj] += qv[ii].x * kv[jj].x + qv[ii].y * kv[jj].y
                               + qv[ii].z * kv[jj].z + qv[ii].w * kv[jj].w;
        }

        // Causal mask (only the diagonal tile has masked entries)
        if (kt == qb) {
#pragma unroll
            for (int ii = 0; ii < 4; ii++)
#pragma unroll
                for (int jj = 0; jj < 4; jj++)
                    if (4*tx + jj > 4*ty + ii) s[ii][jj] = -1e30f;
        }

        // Online softmax. Rows are owned by 16 consecutive lanes (same ty),
        // which sit inside one 16-lane shuffle group.
        float alpha[4];
#pragma unroll
        for (int ii = 0; ii < 4; ii++) {
            float mx = fmaxf(fmaxf(s[ii][0], s[ii][1]), fmaxf(s[ii][2], s[ii][3]));
#pragma unroll
            for (int off = 1; off < 16; off <<= 1)
                mx = fmaxf(mx, __shfl_xor_sync(0xffffffffu, mx, off));
            float mnew = fmaxf(m_i[ii], mx);
            alpha[ii] = __expf(m_i[ii] - mnew);
            float rs = 0.f;
#pragma unroll
            for (int jj = 0; jj < 4; jj++) {
                float p = __expf(s[ii][jj] - mnew);
                s[ii][jj] = p;
                rs += p;
            }
#pragma unroll
            for (int off = 1; off < 16; off <<= 1)
                rs += __shfl_xor_sync(0xffffffffu, rs, off);
            l_i[ii] = l_i[ii] * alpha[ii] + rs;
            m_i[ii] = mnew;
        }

        // Stage P through smem for the PV GEMM.
#pragma unroll
        for (int ii = 0; ii < 4; ii++)
#pragma unroll
            for (int jj = 0; jj < 4; jj++)
                Ps[(4*ty+ii) * PPAD + 4*tx + jj] = s[ii][jj];
        __syncthreads();

        // Rescale accumulators, then out += P @ V.
#pragma unroll
        for (int ii = 0; ii < 4; ii++)
#pragma unroll
            for (int c = 0; c < 8; c++) out[ii][c] *= alpha[ii];

#pragma unroll 4
        for (int j = 0; j < FK; j++) {
            float4 v0 = *(const float4*)(&Vs[j * FPAD + tx * 8]);
            float4 v1 = *(const float4*)(&Vs[j * FPAD + tx * 8 + 4]);
#pragma unroll
            for (int ii = 0; ii < 4; ii++) {
                float p = Ps[(4*ty+ii) * PPAD + j];
                out[ii][0] += p * v0.x; out[ii][1] += p * v0.y;
                out[ii][2] += p * v0.z; out[ii][3] += p * v0.w;
                out[ii][4] += p * v1.x; out[ii][5] += p * v1.y;
                out[ii][6] += p * v1.z; out[ii][7] += p * v1.w;
            }
        }
        __syncthreads();   // before next tile overwrites Ks/Vs/Ps
    }

    // Normalize and write O in [B*S, H*HD] layout.
#pragma unroll
    for (int ii = 0; ii < 4; ii++) {
        float il = 1.f / l_i[ii];
        float* orow = O + (size_t)(qRow0 + 4*ty + ii) * QCOLS + h * PHD + tx * 8;
        *(float4*)(orow)     = make_float4(out[ii][0]*il, out[ii][1]*il,
                                           out[ii][2]*il, out[ii][3]*il);
        *(float4*)(orow + 4) = make_float4(out[ii][4]*il, out[ii][5]*il,
                                           out[ii][6]*il, out[ii][7]*il);
    }
}

// ---------------------------------------------------------------------------
// Launch
// ---------------------------------------------------------------------------
extern "C" void kernel_launch(void* const* d_in, const int* in_sizes, int n_in,
                              void* d_out, int out_size) {
    (void)in_sizes; (void)n_in; (void)out_size;

    const float* x  = (const float*)d_in[0];   // [B,S,D]
    const float* fc = (const float*)d_in[1];   // [S, HD/2]
    const float* fs = (const float*)d_in[2];   // [S, HD/2]
    const float* Wq = (const float*)d_in[3];   // [D, H*HD]
    const float* Wk = (const float*)d_in[4];   // [D, KVH*HD]
    const float* Wv = (const float*)d_in[5];   // [D, KVH*HD]
    const float* Wo = (const float*)d_in[6];   // [H*HD, D]
    float* out = (float*)d_out;                // [B,S,D]

    float *Qb, *Kb, *Vb, *Ob;
    cudaGetSymbolAddress((void**)&Qb, g_Q);
    cudaGetSymbolAddress((void**)&Kb, g_K);
    cudaGetSymbolAddress((void**)&Vb, g_V);
    cudaGetSymbolAddress((void**)&Ob, g_O);

    // 1) QKV projections
    sgemm128<<<dim3(QCOLS/GBN,  ROWS/GBM), 256>>>(x, Wq, Qb, ROWS, QCOLS,  PD);
    sgemm128<<<dim3(KVCOLS/GBN, ROWS/GBM), 256>>>(x, Wk, Kb, ROWS, KVCOLS, PD);
    sgemm128<<<dim3(KVCOLS/GBN, ROWS/GBM), 256>>>(x, Wv, Vb, ROWS, KVCOLS, PD);

    // 2) RoPE (fold 1/sqrt(HD) into Q)
    const float qscale = 0.08838834764831845f;   // 1/sqrt(128)
    {
        int totalQ = ROWS * PH * 64;
        rope_kernel<<<(totalQ + 255) / 256, 256>>>(Qb, fc, fs, PH, totalQ, qscale);
        int totalK = ROWS * PKVH * 64;
        rope_kernel<<<(totalK + 255) / 256, 256>>>(Kb, fc, fs, PKVH, totalK, 1.0f);
    }

    // 3) Fused causal flash attention
    {
        size_t smem = (size_t)(3 * FQ * FPAD + FQ * PPAD) * sizeof(float); // ~115 KB
        cudaFuncSetAttribute(flash_attn,
                             cudaFuncAttributeMaxDynamicSharedMemorySize, (int)smem);
        flash_attn<<<dim3(PS/FQ, PH, PB), 256, smem>>>(Qb, Kb, Vb, Ob);
    }

    // 4) Output projection -> d_out
    sgemm128<<<dim3(PD/GBN, ROWS/GBM), 256>>>(Ob, Wo, out, ROWS, PD, QCOLS);
}

// round 7
// speedup vs baseline: 1.7451x; 1.7439x over previous
#include <cuda_runtime.h>
#include <cuda_bf16.h>
#include <math.h>
#include <stdint.h>

// Problem constants
#define PB  2
#define PS  2048
#define PD  4096
#define PH  32
#define PKVH 8
#define PHD 128
#define ROWS (PB*PS)            // 4096 tokens
#define QCOLS (PH*PHD)          // 4096
#define KVCOLS (PKVH*PHD)       // 1024

// ---------------------------------------------------------------------------
// Scratch (static device allocations — allowed; cudaMalloc is not)
// ---------------------------------------------------------------------------
__device__ float g_Q[(size_t)ROWS * QCOLS];   // 64 MB
__device__ float g_K[(size_t)ROWS * KVCOLS];  // 16 MB
__device__ float g_V[(size_t)ROWS * KVCOLS];  // 16 MB
__device__ float g_O[(size_t)ROWS * QCOLS];   // 64 MB

// ---------------------------------------------------------------------------
// TF32 tensor-core GEMM: C[M,N] = A[M,K] @ B[K,N], row-major fp32 in/out.
// 128x128x16 CTA tile, 256 threads = 8 warps (2x4), 64x32 warp tile,
// mma.sync m16n8k8 tf32. Inputs rounded to tf32 with cvt.rna (NOT truncation).
// Double-buffered smem + register prefetch. M,N %128==0, K %16==0.
// ---------------------------------------------------------------------------
#define TBM 128
#define TBN 128
#define TBK 16
#define TPAD 136   // 128+8: fragment LDS bank = 8*k + idx -> perfect permutation

__device__ __forceinline__ uint32_t f2tf(float x) {
    uint32_t r;
    asm("cvt.rna.tf32.f32 %0, %1;" : "=r"(r) : "f"(x));
    return r;
}

__device__ __forceinline__ void mma_tf32(float c[4], const uint32_t a[4],
                                         const uint32_t b[2]) {
    asm volatile(
        "mma.sync.aligned.m16n8k8.row.col.f32.tf32.tf32.f32 "
        "{%0,%1,%2,%3}, {%4,%5,%6,%7}, {%8,%9}, {%0,%1,%2,%3};"
        : "+f"(c[0]), "+f"(c[1]), "+f"(c[2]), "+f"(c[3])
        : "r"(a[0]), "r"(a[1]), "r"(a[2]), "r"(a[3]),
          "r"(b[0]), "r"(b[1]));
}

__global__ __launch_bounds__(256)
void tf32gemm(const float* __restrict__ A, const float* __restrict__ B,
              float* __restrict__ C, int M, int N, int K) {
    __shared__ uint32_t As[2][TBK][TPAD];   // A transposed: As[k][m]
    __shared__ uint32_t Bs[2][TBK][TPAD];   // Bs[k][n]

    const int tid  = threadIdx.x;
    const int lane = tid & 31;
    const int wid  = tid >> 5;
    const int gID  = lane >> 2;     // 0..7
    const int tig  = lane & 3;      // 0..3
    const int wr   = wid >> 2;      // 0..1  warp row
    const int wc   = wid & 3;       // 0..3  warp col
    const int m0   = wr * 64;
    const int n0   = wc * 32;
    const int rBase = blockIdx.y * TBM;
    const int cBase = blockIdx.x * TBN;

    // Per-thread gmem staging addresses (2 float4 each for A and B)
    const int t0 = tid, t1 = tid + 256;
    const int a_r0 = t0 >> 2, a_k0 = (t0 & 3) * 4;
    const int a_r1 = t1 >> 2, a_k1 = (t1 & 3) * 4;
    const int b_k0 = t0 >> 5, b_c0 = (t0 & 31) * 4;
    const int b_k1 = t1 >> 5, b_c1 = (t1 & 31) * 4;

    float acc[4][4][4];
#pragma unroll
    for (int mf = 0; mf < 4; mf++)
#pragma unroll
        for (int nf = 0; nf < 4; nf++)
#pragma unroll
            for (int r = 0; r < 4; r++) acc[mf][nf][r] = 0.f;

    float4 aR0, aR1, bR0, bR1;

    // prologue: tile 0 gmem -> regs -> (cvt) smem[0]
    aR0 = *(const float4*)(A + (size_t)(rBase + a_r0) * K + a_k0);
    aR1 = *(const float4*)(A + (size_t)(rBase + a_r1) * K + a_k1);
    bR0 = *(const float4*)(B + (size_t)b_k0 * N + cBase + b_c0);
    bR1 = *(const float4*)(B + (size_t)b_k1 * N + cBase + b_c1);
    As[0][a_k0+0][a_r0] = f2tf(aR0.x); As[0][a_k0+1][a_r0] = f2tf(aR0.y);
    As[0][a_k0+2][a_r0] = f2tf(aR0.z); As[0][a_k0+3][a_r0] = f2tf(aR0.w);
    As[0][a_k1+0][a_r1] = f2tf(aR1.x); As[0][a_k1+1][a_r1] = f2tf(aR1.y);
    As[0][a_k1+2][a_r1] = f2tf(aR1.z); As[0][a_k1+3][a_r1] = f2tf(aR1.w);
    Bs[0][b_k0][b_c0+0] = f2tf(bR0.x); Bs[0][b_k0][b_c0+1] = f2tf(bR0.y);
    Bs[0][b_k0][b_c0+2] = f2tf(bR0.z); Bs[0][b_k0][b_c0+3] = f2tf(bR0.w);
    Bs[0][b_k1][b_c1+0] = f2tf(bR1.x); Bs[0][b_k1][b_c1+1] = f2tf(bR1.y);
    Bs[0][b_k1][b_c1+2] = f2tf(bR1.z); Bs[0][b_k1][b_c1+3] = f2tf(bR1.w);
    __syncthreads();

    const int nIter = K / TBK;
    for (int it = 0; it < nIter; it++) {
        const int buf = it & 1;
        const bool more = (it + 1 < nIter);
        if (more) {
            const int k0 = (it + 1) * TBK;
            aR0 = *(const float4*)(A + (size_t)(rBase + a_r0) * K + k0 + a_k0);
            aR1 = *(const float4*)(A + (size_t)(rBase + a_r1) * K + k0 + a_k1);
            bR0 = *(const float4*)(B + (size_t)(k0 + b_k0) * N + cBase + b_c0);
            bR1 = *(const float4*)(B + (size_t)(k0 + b_k1) * N + cBase + b_c1);
        }

#pragma unroll
        for (int kf = 0; kf < 2; kf++) {
            const int kb = kf * 8;
            uint32_t aF[4][4], bF[4][2];
#pragma unroll
            for (int mf = 0; mf < 4; mf++) {
                const int mr = m0 + mf * 16 + gID;
                aF[mf][0] = As[buf][kb + tig    ][mr    ];
                aF[mf][1] = As[buf][kb + tig    ][mr + 8];
                aF[mf][2] = As[buf][kb + tig + 4][mr    ];
                aF[mf][3] = As[buf][kb + tig + 4][mr + 8];
            }
#pragma unroll
            for (int nf = 0; nf < 4; nf++) {
                const int nc = n0 + nf * 8 + gID;
                bF[nf][0] = Bs[buf][kb + tig    ][nc];
                bF[nf][1] = Bs[buf][kb + tig + 4][nc];
            }
#pragma unroll
            for (int mf = 0; mf < 4; mf++)
#pragma unroll
                for (int nf = 0; nf < 4; nf++)
                    mma_tf32(acc[mf][nf], aF[mf], bF[nf]);
        }

        if (more) {
            const int nb = buf ^ 1;
            As[nb][a_k0+0][a_r0] = f2tf(aR0.x); As[nb][a_k0+1][a_r0] = f2tf(aR0.y);
            As[nb][a_k0+2][a_r0] = f2tf(aR0.z); As[nb][a_k0+3][a_r0] = f2tf(aR0.w);
            As[nb][a_k1+0][a_r1] = f2tf(aR1.x); As[nb][a_k1+1][a_r1] = f2tf(aR1.y);
            As[nb][a_k1+2][a_r1] = f2tf(aR1.z); As[nb][a_k1+3][a_r1] = f2tf(aR1.w);
            Bs[nb][b_k0][b_c0+0] = f2tf(bR0.x); Bs[nb][b_k0][b_c0+1] = f2tf(bR0.y);
            Bs[nb][b_k0][b_c0+2] = f2tf(bR0.z); Bs[nb][b_k0][b_c0+3] = f2tf(bR0.w);
            Bs[nb][b_k1][b_c1+0] = f2tf(bR1.x); Bs[nb][b_k1][b_c1+1] = f2tf(bR1.y);
            Bs[nb][b_k1][b_c1+2] = f2tf(bR1.z); Bs[nb][b_k1][b_c1+3] = f2tf(bR1.w);
        }
        __syncthreads();
    }

    // Epilogue: c0/c1 are adjacent columns -> float2 stores, coalesced per quad
#pragma unroll
    for (int mf = 0; mf < 4; mf++) {
#pragma unroll
        for (int nf = 0; nf < 4; nf++) {
            const int row = rBase + m0 + mf * 16 + gID;
            const int col = cBase + n0 + nf * 8 + tig * 2;
            *(float2*)(C + (size_t)row * N + col) =
                make_float2(acc[mf][nf][0], acc[mf][nf][1]);
            *(float2*)(C + (size_t)(row + 8) * N + col) =
                make_float2(acc[mf][nf][2], acc[mf][nf][3]);
        }
    }
}

// ---------------------------------------------------------------------------
// RoPE (interleaved even/odd pairs), optional uniform scale (folds 1/sqrt(HD)
// into Q). t: [rows, nHeads*128] row-major; rows = B*S; seq index = row % S.
// ---------------------------------------------------------------------------
__global__ void rope_kernel(float* __restrict__ t,
                            const float* __restrict__ cos_t,
                            const float* __restrict__ sin_t,
                            int nHeads, int total, float scale) {
    int idx = blockIdx.x * blockDim.x + threadIdx.x;
    if (idx >= total) return;
    int pair = idx & 63;                 // HD/2 = 64
    int head = (idx >> 6) % nHeads;
    int row  = idx / (64 * nHeads);
    int s    = row & (PS - 1);
    float c  = cos_t[s * 64 + pair];
    float sn = sin_t[s * 64 + pair];
    float2* p = (float2*)(t + (size_t)row * (nHeads * 128) + head * 128 + pair * 2);
    float2 v = *p;
    float vr = (v.x * c - v.y * sn) * scale;
    float vi = (v.x * sn + v.y * c) * scale;
    *p = make_float2(vr, vi);
}

// ---------------------------------------------------------------------------
// Fused causal flash attention, fp32. GQA REP=4.
// grid = (S/64, H, B); 256 threads = 16x16; each thread: 4 q-rows x (4 score
// cols | 8 out cols). Q pre-scaled by 1/sqrt(HD).
// ---------------------------------------------------------------------------
#define FQ 64
#define FK 64
#define FPAD 132   // row stride for 128-wide tiles
#define PPAD 65    // row stride for P tile

__global__ __launch_bounds__(256, 1)
void flash_attn(const float* __restrict__ Q, const float* __restrict__ K,
                const float* __restrict__ V, float* __restrict__ O) {
    extern __shared__ float sm[];
    float* Qs = sm;                    // [64][132]
    float* Ks = Qs + FQ * FPAD;        // [64][132]
    float* Vs = Ks + FK * FPAD;        // [64][132]
    float* Ps = Vs + FK * FPAD;        // [64][65]

    const int tid = threadIdx.x;
    const int tx  = tid & 15;
    const int ty  = tid >> 4;
    const int qb  = blockIdx.x;
    const int h   = blockIdx.y;
    const int b   = blockIdx.z;
    const int kvh = h >> 2;            // REP = 4

    const int qRow0 = b * PS + qb * FQ;
    const float* Qg = Q + (size_t)qRow0 * QCOLS + h * PHD;

#pragma unroll
    for (int r = 0; r < 8; r++) {
        int t  = tid + r * 256;
        int i  = t >> 5;
        int d4 = t & 31;
        *(float4*)(&Qs[i * FPAD + d4 * 4]) =
            *(const float4*)(Qg + (size_t)i * QCOLS + d4 * 4);
    }

    float out[4][8];
    float m_i[4], l_i[4];
#pragma unroll
    for (int ii = 0; ii < 4; ii++) {
        m_i[ii] = -1e30f; l_i[ii] = 0.f;
#pragma unroll
        for (int c = 0; c < 8; c++) out[ii][c] = 0.f;
    }
    __syncthreads();

    const int nkt = qb + 1;   // causal: only k-tiles up to the diagonal
    for (int kt = 0; kt < nkt; kt++) {
        const int kRow0 = b * PS + kt * FK;
        const float* Kg = K + (size_t)kRow0 * KVCOLS + kvh * PHD;
        const float* Vg = V + (size_t)kRow0 * KVCOLS + kvh * PHD;
#pragma unroll
        for (int r = 0; r < 8; r++) {
            int t  = tid + r * 256;
            int j  = t >> 5;
            int d4 = t & 31;
            *(float4*)(&Ks[j * FPAD + d4 * 4]) =
                *(const float4*)(Kg + (size_t)j * KVCOLS + d4 * 4);
            *(float4*)(&Vs[j * FPAD + d4 * 4]) =
                *(const float4*)(Vg + (size_t)j * KVCOLS + d4 * 4);
        }
        __syncthreads();

        float s[4][4];
#pragma unroll
        for (int ii = 0; ii < 4; ii++)
#pragma unroll
            for (int jj = 0; jj < 4; jj++) s[ii][jj] = 0.f;

#pragma unroll 8
        for (int d4 = 0; d4 < 32; d4++) {
            float4 qv[4], kv[4];
#pragma unroll
            for (int ii = 0; ii < 4; ii++)
                qv[ii] = *(const float4*)(&Qs[(4*ty+ii) * FPAD + d4 * 4]);
#pragma unroll
            for (int jj = 0; jj < 4; jj++)
                kv[jj] = *(const float4*)(&Ks[(4*tx+jj) * FPAD + d4 * 4]);
#pragma unroll
            for (int ii = 0; ii < 4; ii++)
#pragma unroll
                for (int jj = 0; jj < 4; jj++)
                    s[ii][jj] += qv[ii].x * kv[jj].x + qv[ii].y * kv[jj].y
                               + qv[ii].z * kv[jj].z + qv[ii].w * kv[jj].w;
        }

        if (kt == qb) {
#pragma unroll
            for (int ii = 0; ii < 4; ii++)
#pragma unroll
                for (int jj = 0; jj < 4; jj++)
                    if (4*tx + jj > 4*ty + ii) s[ii][jj] = -1e30f;
        }

        float alpha[4];
#pragma unroll
        for (int ii = 0; ii < 4; ii++) {
            float mx = fmaxf(fmaxf(s[ii][0], s[ii][1]), fmaxf(s[ii][2], s[ii][3]));
#pragma unroll
            for (int off = 1; off < 16; off <<= 1)
                mx = fmaxf(mx, __shfl_xor_sync(0xffffffffu, mx, off));
            float mnew = fmaxf(m_i[ii], mx);
            alpha[ii] = __expf(m_i[ii] - mnew);
            float rs = 0.f;
#pragma unroll
            for (int jj = 0; jj < 4; jj++) {
                float p = __expf(s[ii][jj] - mnew);
                s[ii][jj] = p;
                rs += p;
            }
#pragma unroll
            for (int off = 1; off < 16; off <<= 1)
                rs += __shfl_xor_sync(0xffffffffu, rs, off);
            l_i[ii] = l_i[ii] * alpha[ii] + rs;
            m_i[ii] = mnew;
        }

#pragma unroll
        for (int ii = 0; ii < 4; ii++)
#pragma unroll
            for (int jj = 0; jj < 4; jj++)
                Ps[(4*ty+ii) * PPAD + 4*tx + jj] = s[ii][jj];
        __syncthreads();

#pragma unroll
        for (int ii = 0; ii < 4; ii++)
#pragma unroll
            for (int c = 0; c < 8; c++) out[ii][c] *= alpha[ii];

#pragma unroll 4
        for (int j = 0; j < FK; j++) {
            float4 v0 = *(const float4*)(&Vs[j * FPAD + tx * 8]);
            float4 v1 = *(const float4*)(&Vs[j * FPAD + tx * 8 + 4]);
#pragma unroll
            for (int ii = 0; ii < 4; ii++) {
                float p = Ps[(4*ty+ii) * PPAD + j];
                out[ii][0] += p * v0.x; out[ii][1] += p * v0.y;
                out[ii][2] += p * v0.z; out[ii][3] += p * v0.w;
                out[ii][4] += p * v1.x; out[ii][5] += p * v1.y;
                out[ii][6] += p * v1.z; out[ii][7] += p * v1.w;
            }
        }
        __syncthreads();
    }

#pragma unroll
    for (int ii = 0; ii < 4; ii++) {
        float il = 1.f / l_i[ii];
        float* orow = O + (size_t)(qRow0 + 4*ty + ii) * QCOLS + h * PHD + tx * 8;
        *(float4*)(orow)     = make_float4(out[ii][0]*il, out[ii][1]*il,
                                           out[ii][2]*il, out[ii][3]*il);
        *(float4*)(orow + 4) = make_float4(out[ii][4]*il, out[ii][5]*il,
                                           out[ii][6]*il, out[ii][7]*il);
    }
}

// ---------------------------------------------------------------------------
// Launch
// ---------------------------------------------------------------------------
extern "C" void kernel_launch(void* const* d_in, const int* in_sizes, int n_in,
                              void* d_out, int out_size) {
    (void)in_sizes; (void)n_in; (void)out_size;

    const float* x  = (const float*)d_in[0];   // [B,S,D]
    const float* fc = (const float*)d_in[1];   // [S, HD/2]
    const float* fs = (const float*)d_in[2];   // [S, HD/2]
    const float* Wq = (const float*)d_in[3];   // [D, H*HD]
    const float* Wk = (const float*)d_in[4];   // [D, KVH*HD]
    const float* Wv = (const float*)d_in[5];   // [D, KVH*HD]
    const float* Wo = (const float*)d_in[6];   // [H*HD, D]
    float* out = (float*)d_out;                // [B,S,D]

    float *Qb, *Kb, *Vb, *Ob;
    cudaGetSymbolAddress((void**)&Qb, g_Q);
    cudaGetSymbolAddress((void**)&Kb, g_K);
    cudaGetSymbolAddress((void**)&Vb, g_V);
    cudaGetSymbolAddress((void**)&Ob, g_O);

    // 1) QKV projections (TF32 tensor cores)
    tf32gemm<<<dim3(QCOLS/TBN,  ROWS/TBM), 256>>>(x, Wq, Qb, ROWS, QCOLS,  PD);
    tf32gemm<<<dim3(KVCOLS/TBN, ROWS/TBM), 256>>>(x, Wk, Kb, ROWS, KVCOLS, PD);
    tf32gemm<<<dim3(KVCOLS/TBN, ROWS/TBM), 256>>>(x, Wv, Vb, ROWS, KVCOLS, PD);

    // 2) RoPE (fold 1/sqrt(HD) into Q)
    const float qscale = 0.08838834764831845f;   // 1/sqrt(128)
    {
        int totalQ = ROWS * PH * 64;
        rope_kernel<<<(totalQ + 255) / 256, 256>>>(Qb, fc, fs, PH, totalQ, qscale);
        int totalK = ROWS * PKVH * 64;
        rope_kernel<<<(totalK + 255) / 256, 256>>>(Kb, fc, fs, PKVH, totalK, 1.0f);
    }

    // 3) Fused causal flash attention (fp32)
    {
        size_t smem = (size_t)(3 * FQ * FPAD + FQ * PPAD) * sizeof(float); // ~115 KB
        cudaFuncSetAttribute(flash_attn,
                             cudaFuncAttributeMaxDynamicSharedMemorySize, (int)smem);
        flash_attn<<<dim3(PS/FQ, PH, PB), 256, smem>>>(Qb, Kb, Vb, Ob);
    }

    // 4) Output projection -> d_out (TF32 tensor cores)
    tf32gemm<<<dim3(PD/TBN, ROWS/TBM), 256>>>(Ob, Wo, out, ROWS, PD, QCOLS);
}

// round 8
// speedup vs baseline: 3.3307x; 1.9086x over previous
#include <cuda_runtime.h>
#include <cuda_bf16.h>
#include <math.h>
#include <stdint.h>

// Problem constants
#define PB  2
#define PS  2048
#define PD  4096
#define PH  32
#define PKVH 8
#define PHD 128
#define ROWS (PB*PS)            // 4096 tokens
#define QCOLS (PH*PHD)          // 4096
#define KVCOLS (PKVH*PHD)       // 1024

// ---------------------------------------------------------------------------
// Scratch (static device allocations)
// ---------------------------------------------------------------------------
__device__ float g_Q[(size_t)ROWS * QCOLS];   // 64 MB
__device__ float g_K[(size_t)ROWS * KVCOLS];  // 16 MB
__device__ float g_V[(size_t)ROWS * KVCOLS];  // 16 MB
__device__ float g_O[(size_t)ROWS * QCOLS];   // 64 MB

// ---------------------------------------------------------------------------
// TF32 helpers
// ---------------------------------------------------------------------------
__device__ __forceinline__ uint32_t f2tf(float x) {
    uint32_t r;
    asm("cvt.rna.tf32.f32 %0, %1;" : "=r"(r) : "f"(x));
    return r;
}

__device__ __forceinline__ void mma_tf32(float c[4], const uint32_t a[4],
                                         const uint32_t b[2]) {
    asm volatile(
        "mma.sync.aligned.m16n8k8.row.col.f32.tf32.tf32.f32 "
        "{%0,%1,%2,%3}, {%4,%5,%6,%7}, {%8,%9}, {%0,%1,%2,%3};"
        : "+f"(c[0]), "+f"(c[1]), "+f"(c[2]), "+f"(c[3])
        : "r"(a[0]), "r"(a[1]), "r"(a[2]), "r"(a[3]),
          "r"(b[0]), "r"(b[1]));
}

// ---------------------------------------------------------------------------
// TF32 tensor-core GEMM: C[M,N] = A[M,K] @ B[K,N], row-major fp32 in/out.
// (unchanged from round 7)
// ---------------------------------------------------------------------------
#define TBM 128
#define TBN 128
#define TBK 16
#define TPAD 136

__global__ __launch_bounds__(256)
void tf32gemm(const float* __restrict__ A, const float* __restrict__ B,
              float* __restrict__ C, int M, int N, int K) {
    __shared__ uint32_t As[2][TBK][TPAD];   // A transposed: As[k][m]
    __shared__ uint32_t Bs[2][TBK][TPAD];   // Bs[k][n]

    const int tid  = threadIdx.x;
    const int lane = tid & 31;
    const int wid  = tid >> 5;
    const int gID  = lane >> 2;
    const int tig  = lane & 3;
    const int wr   = wid >> 2;
    const int wc   = wid & 3;
    const int m0   = wr * 64;
    const int n0   = wc * 32;
    const int rBase = blockIdx.y * TBM;
    const int cBase = blockIdx.x * TBN;

    const int t0 = tid, t1 = tid + 256;
    const int a_r0 = t0 >> 2, a_k0 = (t0 & 3) * 4;
    const int a_r1 = t1 >> 2, a_k1 = (t1 & 3) * 4;
    const int b_k0 = t0 >> 5, b_c0 = (t0 & 31) * 4;
    const int b_k1 = t1 >> 5, b_c1 = (t1 & 31) * 4;

    float acc[4][4][4];
#pragma unroll
    for (int mf = 0; mf < 4; mf++)
#pragma unroll
        for (int nf = 0; nf < 4; nf++)
#pragma unroll
            for (int r = 0; r < 4; r++) acc[mf][nf][r] = 0.f;

    float4 aR0, aR1, bR0, bR1;

    aR0 = *(const float4*)(A + (size_t)(rBase + a_r0) * K + a_k0);
    aR1 = *(const float4*)(A + (size_t)(rBase + a_r1) * K + a_k1);
    bR0 = *(const float4*)(B + (size_t)b_k0 * N + cBase + b_c0);
    bR1 = *(const float4*)(B + (size_t)b_k1 * N + cBase + b_c1);
    As[0][a_k0+0][a_r0] = f2tf(aR0.x); As[0][a_k0+1][a_r0] = f2tf(aR0.y);
    As[0][a_k0+2][a_r0] = f2tf(aR0.z); As[0][a_k0+3][a_r0] = f2tf(aR0.w);
    As[0][a_k1+0][a_r1] = f2tf(aR1.x); As[0][a_k1+1][a_r1] = f2tf(aR1.y);
    As[0][a_k1+2][a_r1] = f2tf(aR1.z); As[0][a_k1+3][a_r1] = f2tf(aR1.w);
    Bs[0][b_k0][b_c0+0] = f2tf(bR0.x); Bs[0][b_k0][b_c0+1] = f2tf(bR0.y);
    Bs[0][b_k0][b_c0+2] = f2tf(bR0.z); Bs[0][b_k0][b_c0+3] = f2tf(bR0.w);
    Bs[0][b_k1][b_c1+0] = f2tf(bR1.x); Bs[0][b_k1][b_c1+1] = f2tf(bR1.y);
    Bs[0][b_k1][b_c1+2] = f2tf(bR1.z); Bs[0][b_k1][b_c1+3] = f2tf(bR1.w);
    __syncthreads();

    const int nIter = K / TBK;
    for (int it = 0; it < nIter; it++) {
        const int buf = it & 1;
        const bool more = (it + 1 < nIter);
        if (more) {
            const int k0 = (it + 1) * TBK;
            aR0 = *(const float4*)(A + (size_t)(rBase + a_r0) * K + k0 + a_k0);
            aR1 = *(const float4*)(A + (size_t)(rBase + a_r1) * K + k0 + a_k1);
            bR0 = *(const float4*)(B + (size_t)(k0 + b_k0) * N + cBase + b_c0);
            bR1 = *(const float4*)(B + (size_t)(k0 + b_k1) * N + cBase + b_c1);
        }

#pragma unroll
        for (int kf = 0; kf < 2; kf++) {
            const int kb = kf * 8;
            uint32_t aF[4][4], bF[4][2];
#pragma unroll
            for (int mf = 0; mf < 4; mf++) {
                const int mr = m0 + mf * 16 + gID;
                aF[mf][0] = As[buf][kb + tig    ][mr    ];
                aF[mf][1] = As[buf][kb + tig    ][mr + 8];
                aF[mf][2] = As[buf][kb + tig + 4][mr    ];
                aF[mf][3] = As[buf][kb + tig + 4][mr + 8];
            }
#pragma unroll
            for (int nf = 0; nf < 4; nf++) {
                const int nc = n0 + nf * 8 + gID;
                bF[nf][0] = Bs[buf][kb + tig    ][nc];
                bF[nf][1] = Bs[buf][kb + tig + 4][nc];
            }
#pragma unroll
            for (int mf = 0; mf < 4; mf++)
#pragma unroll
                for (int nf = 0; nf < 4; nf++)
                    mma_tf32(acc[mf][nf], aF[mf], bF[nf]);
        }

        if (more) {
            const int nb = buf ^ 1;
            As[nb][a_k0+0][a_r0] = f2tf(aR0.x); As[nb][a_k0+1][a_r0] = f2tf(aR0.y);
            As[nb][a_k0+2][a_r0] = f2tf(aR0.z); As[nb][a_k0+3][a_r0] = f2tf(aR0.w);
            As[nb][a_k1+0][a_r1] = f2tf(aR1.x); As[nb][a_k1+1][a_r1] = f2tf(aR1.y);
            As[nb][a_k1+2][a_r1] = f2tf(aR1.z); As[nb][a_k1+3][a_r1] = f2tf(aR1.w);
            Bs[nb][b_k0][b_c0+0] = f2tf(bR0.x); Bs[nb][b_k0][b_c0+1] = f2tf(bR0.y);
            Bs[nb][b_k0][b_c0+2] = f2tf(bR0.z); Bs[nb][b_k0][b_c0+3] = f2tf(bR0.w);
            Bs[nb][b_k1][b_c1+0] = f2tf(bR1.x); Bs[nb][b_k1][b_c1+1] = f2tf(bR1.y);
            Bs[nb][b_k1][b_c1+2] = f2tf(bR1.z); Bs[nb][b_k1][b_c1+3] = f2tf(bR1.w);
        }
        __syncthreads();
    }

#pragma unroll
    for (int mf = 0; mf < 4; mf++) {
#pragma unroll
        for (int nf = 0; nf < 4; nf++) {
            const int row = rBase + m0 + mf * 16 + gID;
            const int col = cBase + n0 + nf * 8 + tig * 2;
            *(float2*)(C + (size_t)row * N + col) =
                make_float2(acc[mf][nf][0], acc[mf][nf][1]);
            *(float2*)(C + (size_t)(row + 8) * N + col) =
                make_float2(acc[mf][nf][2], acc[mf][nf][3]);
        }
    }
}

// ---------------------------------------------------------------------------
// RoPE + tf32 pre-rounding of the output (Q and K are consumed by the tf32
// flash kernel, so we round here with cvt.rna — flash then copies raw bits).
// ---------------------------------------------------------------------------
__global__ void rope_kernel(float* __restrict__ t,
                            const float* __restrict__ cos_t,
                            const float* __restrict__ sin_t,
                            int nHeads, int total, float scale) {
    int idx = blockIdx.x * blockDim.x + threadIdx.x;
    if (idx >= total) return;
    int pair = idx & 63;                 // HD/2 = 64
    int head = (idx >> 6) % nHeads;
    int row  = idx / (64 * nHeads);
    int s    = row & (PS - 1);
    float c  = cos_t[s * 64 + pair];
    float sn = sin_t[s * 64 + pair];
    float2* p = (float2*)(t + (size_t)row * (nHeads * 128) + head * 128 + pair * 2);
    float2 v = *p;
    float vr = (v.x * c - v.y * sn) * scale;
    float vi = (v.x * sn + v.y * c) * scale;
    *p = make_float2(__uint_as_float(f2tf(vr)), __uint_as_float(f2tf(vi)));
}

// Pre-round V to tf32 values (in fp32 storage), so the flash kernel can use
// the bits directly as tf32 operands without a systematic truncation bias.
__global__ void tf32_round_kernel(float* __restrict__ t, int n4) {
    int i = blockIdx.x * blockDim.x + threadIdx.x;
    if (i >= n4) return;
    float4 v = ((float4*)t)[i];
    v.x = __uint_as_float(f2tf(v.x));
    v.y = __uint_as_float(f2tf(v.y));
    v.z = __uint_as_float(f2tf(v.z));
    v.w = __uint_as_float(f2tf(v.w));
    ((float4*)t)[i] = v;
}

// ---------------------------------------------------------------------------
// Tensor-core causal flash attention (tf32 mma, fp32 accum, fp32 softmax).
// BQ=128 q-rows per CTA, BK=64 kv per iteration, HD=128. 8 warps; warp w owns
// q-rows [16w,16w+16) -> softmax rows live inside 4-lane shuffle groups.
// Q fragments cached in registers across all k-tiles. P staged via a
// warp-private smem region (only __syncwarp around it).
// Q pre-scaled by 1/sqrt(HD); Q,K,V pre-rounded to tf32 values.
// ---------------------------------------------------------------------------
#define BQ 128
#define BK 64
#define KPAD 132   // banks: gID*4 + tig  -> conflict-free B/K frag loads
#define VPAD 136   // banks: tig*8 + gID  -> conflict-free V frag loads
#define PPAD 68    // banks: gID*4 + tig  -> conflict-free P frag loads

__global__ __launch_bounds__(256, 1)
void flash_attn_tc(const float* __restrict__ Q, const float* __restrict__ K,
                   const float* __restrict__ V, float* __restrict__ O) {
    extern __shared__ float sm[];
    float* Ks = sm;                    // [64][132]
    float* Vs = Ks + BK * KPAD;        // [64][136]
    float* Ps = Vs + BK * VPAD;        // [128][68], rows [16w,16w+16) per warp

    const int tid  = threadIdx.x;
    const int lane = tid & 31;
    const int wid  = tid >> 5;
    const int gID  = lane >> 2;        // 0..7
    const int tig  = lane & 3;         // 0..3
    const int qb   = blockIdx.x;
    const int h    = blockIdx.y;
    const int b    = blockIdx.z;
    const int kvh  = h >> 2;           // REP = 4
    const int m0   = wid * 16;
    const int qRow0 = b * PS + qb * BQ;

    // --- Q fragments (all 16 k-steps) cached in registers ---
    uint32_t aQ[16][4];
    {
        const float* Qg = Q + (size_t)(qRow0 + m0) * QCOLS + h * PHD;
#pragma unroll
        for (int kb = 0; kb < 16; kb++) {
            const int c = kb * 8 + tig;
            aQ[kb][0] = __float_as_uint(Qg[(size_t)gID       * QCOLS + c    ]);
            aQ[kb][1] = __float_as_uint(Qg[(size_t)(gID + 8) * QCOLS + c    ]);
            aQ[kb][2] = __float_as_uint(Qg[(size_t)gID       * QCOLS + c + 4]);
            aQ[kb][3] = __float_as_uint(Qg[(size_t)(gID + 8) * QCOLS + c + 4]);
        }
    }

    float oAcc[16][4];
#pragma unroll
    for (int nf = 0; nf < 16; nf++)
#pragma unroll
        for (int r = 0; r < 4; r++) oAcc[nf][r] = 0.f;
    float m_i[2] = {-1e30f, -1e30f};
    float l_i[2] = {0.f, 0.f};

    const int nkt = 2 * qb + 2;
    for (int kt = 0; kt < nkt; kt++) {
        __syncthreads();   // previous tile's Ks/Vs fully consumed
        {
            const int kRow0 = b * PS + kt * BK;
            const float* Kg = K + (size_t)kRow0 * KVCOLS + kvh * PHD;
            const float* Vg = V + (size_t)kRow0 * KVCOLS + kvh * PHD;
#pragma unroll
            for (int r = 0; r < 8; r++) {
                int t  = tid + r * 256;
                int j  = t >> 5;
                int c4 = (t & 31) * 4;
                *(float4*)(&Ks[j * KPAD + c4]) =
                    *(const float4*)(Kg + (size_t)j * KVCOLS + c4);
                *(float4*)(&Vs[j * VPAD + c4]) =
                    *(const float4*)(Vg + (size_t)j * KVCOLS + c4);
            }
        }
        __syncthreads();

        // --- S = Q @ K^T (16x64 per warp) ---
        float sAcc[8][4];
#pragma unroll
        for (int nf = 0; nf < 8; nf++)
#pragma unroll
            for (int r = 0; r < 4; r++) sAcc[nf][r] = 0.f;

#pragma unroll
        for (int kb = 0; kb < 16; kb++) {
            const int kc = kb * 8 + tig;
#pragma unroll
            for (int nf = 0; nf < 8; nf++) {
                uint32_t bK[2];
                bK[0] = __float_as_uint(Ks[(nf * 8 + gID) * KPAD + kc    ]);
                bK[1] = __float_as_uint(Ks[(nf * 8 + gID) * KPAD + kc + 4]);
                mma_tf32(sAcc[nf], aQ[kb], bK);
            }
        }

        // --- causal mask (only the two diagonal-region tiles) ---
        if (kt >= 2 * qb) {
            const int r0 = qb * BQ + m0 + gID;
            const int r1 = r0 + 8;
            const int cb = kt * BK + 2 * tig;
#pragma unroll
            for (int nf = 0; nf < 8; nf++) {
                const int c0 = cb + nf * 8;
                if (c0     > r0) sAcc[nf][0] = -1e30f;
                if (c0 + 1 > r0) sAcc[nf][1] = -1e30f;
                if (c0     > r1) sAcc[nf][2] = -1e30f;
                if (c0 + 1 > r1) sAcc[nf][3] = -1e30f;
            }
        }

        // --- online softmax (rows gID and gID+8; reduce over 4 tig lanes) ---
        float mx0 = -1e30f, mx1 = -1e30f;
#pragma unroll
        for (int nf = 0; nf < 8; nf++) {
            mx0 = fmaxf(mx0, fmaxf(sAcc[nf][0], sAcc[nf][1]));
            mx1 = fmaxf(mx1, fmaxf(sAcc[nf][2], sAcc[nf][3]));
        }
        mx0 = fmaxf(mx0, __shfl_xor_sync(0xffffffffu, mx0, 1));
        mx0 = fmaxf(mx0, __shfl_xor_sync(0xffffffffu, mx0, 2));
        mx1 = fmaxf(mx1, __shfl_xor_sync(0xffffffffu, mx1, 1));
        mx1 = fmaxf(mx1, __shfl_xor_sync(0xffffffffu, mx1, 2));

        const float mn0 = fmaxf(m_i[0], mx0);
        const float mn1 = fmaxf(m_i[1], mx1);
        const float al0 = __expf(m_i[0] - mn0);
        const float al1 = __expf(m_i[1] - mn1);

        float rs0 = 0.f, rs1 = 0.f;
#pragma unroll
        for (int nf = 0; nf < 8; nf++) {
            sAcc[nf][0] = __expf(sAcc[nf][0] - mn0);
            sAcc[nf][1] = __expf(sAcc[nf][1] - mn0);
            sAcc[nf][2] = __expf(sAcc[nf][2] - mn1);
            sAcc[nf][3] = __expf(sAcc[nf][3] - mn1);
            rs0 += sAcc[nf][0] + sAcc[nf][1];
            rs1 += sAcc[nf][2] + sAcc[nf][3];
        }
        rs0 += __shfl_xor_sync(0xffffffffu, rs0, 1);
        rs0 += __shfl_xor_sync(0xffffffffu, rs0, 2);
        rs1 += __shfl_xor_sync(0xffffffffu, rs1, 1);
        rs1 += __shfl_xor_sync(0xffffffffu, rs1, 2);

        l_i[0] = l_i[0] * al0 + rs0;
        l_i[1] = l_i[1] * al1 + rs1;
        m_i[0] = mn0;
        m_i[1] = mn1;

        // rescale output accumulators
#pragma unroll
        for (int nf = 0; nf < 16; nf++) {
            oAcc[nf][0] *= al0; oAcc[nf][1] *= al0;
            oAcc[nf][2] *= al1; oAcc[nf][3] *= al1;
        }

        // --- stage P (tf32-rounded) into warp-private smem rows ---
#pragma unroll
        for (int nf = 0; nf < 8; nf++) {
            const int col = nf * 8 + 2 * tig;
            *(uint2*)(&Ps[(m0 + gID    ) * PPAD + col]) =
                make_uint2(f2tf(sAcc[nf][0]), f2tf(sAcc[nf][1]));
            *(uint2*)(&Ps[(m0 + gID + 8) * PPAD + col]) =
                make_uint2(f2tf(sAcc[nf][2]), f2tf(sAcc[nf][3]));
        }
        __syncwarp();

        // --- O += P @ V (16x128 per warp) ---
#pragma unroll
        for (int kb = 0; kb < 8; kb++) {
            const int kc = kb * 8 + tig;
            uint32_t aP[4];
            aP[0] = __float_as_uint(Ps[(m0 + gID    ) * PPAD + kc    ]);
            aP[1] = __float_as_uint(Ps[(m0 + gID + 8) * PPAD + kc    ]);
            aP[2] = __float_as_uint(Ps[(m0 + gID    ) * PPAD + kc + 4]);
            aP[3] = __float_as_uint(Ps[(m0 + gID + 8) * PPAD + kc + 4]);
#pragma unroll
            for (int nf = 0; nf < 16; nf++) {
                uint32_t bV[2];
                bV[0] = __float_as_uint(Vs[(kc    ) * VPAD + nf * 8 + gID]);
                bV[1] = __float_as_uint(Vs[(kc + 4) * VPAD + nf * 8 + gID]);
                mma_tf32(oAcc[nf], aP, bV);
            }
        }
        __syncwarp();   // WAR: next iteration rewrites Ps
    }

    // --- epilogue: normalize, write O[B*S, H*HD] ---
    const float il0 = 1.f / l_i[0];
    const float il1 = 1.f / l_i[1];
    float* Og = O + (size_t)(qRow0 + m0) * QCOLS + h * PHD;
#pragma unroll
    for (int nf = 0; nf < 16; nf++) {
        const int col = nf * 8 + 2 * tig;
        *(float2*)(Og + (size_t)gID       * QCOLS + col) =
            make_float2(oAcc[nf][0] * il0, oAcc[nf][1] * il0);
        *(float2*)(Og + (size_t)(gID + 8) * QCOLS + col) =
            make_float2(oAcc[nf][2] * il1, oAcc[nf][3] * il1);
    }
}

// ---------------------------------------------------------------------------
// Launch
// ---------------------------------------------------------------------------
extern "C" void kernel_launch(void* const* d_in, const int* in_sizes, int n_in,
                              void* d_out, int out_size) {
    (void)in_sizes; (void)n_in; (void)out_size;

    const float* x  = (const float*)d_in[0];   // [B,S,D]
    const float* fc = (const float*)d_in[1];   // [S, HD/2]
    const float* fs = (const float*)d_in[2];   // [S, HD/2]
    const float* Wq = (const float*)d_in[3];   // [D, H*HD]
    const float* Wk = (const float*)d_in[4];   // [D, KVH*HD]
    const float* Wv = (const float*)d_in[5];   // [D, KVH*HD]
    const float* Wo = (const float*)d_in[6];   // [H*HD, D]
    float* out = (float*)d_out;                // [B,S,D]

    float *Qb, *Kb, *Vb, *Ob;
    cudaGetSymbolAddress((void**)&Qb, g_Q);
    cudaGetSymbolAddress((void**)&Kb, g_K);
    cudaGetSymbolAddress((void**)&Vb, g_V);
    cudaGetSymbolAddress((void**)&Ob, g_O);

    // 1) QKV projections (TF32 tensor cores)
    tf32gemm<<<dim3(QCOLS/TBN,  ROWS/TBM), 256>>>(x, Wq, Qb, ROWS, QCOLS,  PD);
    tf32gemm<<<dim3(KVCOLS/TBN, ROWS/TBM), 256>>>(x, Wk, Kb, ROWS, KVCOLS, PD);
    tf32gemm<<<dim3(KVCOLS/TBN, ROWS/TBM), 256>>>(x, Wv, Vb, ROWS, KVCOLS, PD);

    // 2) RoPE (fold 1/sqrt(HD) into Q; outputs tf32-rounded) + V rounding
    const float qscale = 0.08838834764831845f;   // 1/sqrt(128)
    {
        int totalQ = ROWS * PH * 64;
        rope_kernel<<<(totalQ + 255) / 256, 256>>>(Qb, fc, fs, PH, totalQ, qscale);
        int totalK = ROWS * PKVH * 64;
        rope_kernel<<<(totalK + 255) / 256, 256>>>(Kb, fc, fs, PKVH, totalK, 1.0f);
        int n4 = (ROWS * KVCOLS) / 4;
        tf32_round_kernel<<<(n4 + 255) / 256, 256>>>(Vb, n4);
    }

    // 3) Tensor-core causal flash attention
    {
        size_t smem = (size_t)(BK * KPAD + BK * VPAD + BQ * PPAD) * sizeof(float);
        cudaFuncSetAttribute(flash_attn_tc,
                             cudaFuncAttributeMaxDynamicSharedMemorySize, (int)smem);
        flash_attn_tc<<<dim3(PS/BQ, PH, PB), 256, smem>>>(Qb, Kb, Vb, Ob);
    }

    // 4) Output projection -> d_out (TF32 tensor cores)
    tf32gemm<<<dim3(PD/TBN, ROWS/TBM), 256>>>(Ob, Wo, out, ROWS, PD, QCOLS);
}